// round 9
// baseline (speedup 1.0000x reference)
#include <cuda_runtime.h>
#include <math.h>

#define NPOS 32768      // 32^3 fine positions
#define NCELL 4096      // 16^3 coarse cells
#define CIN 64
#define COFF 81         // 3 * 27 offset channels
#define COUT 32

// Scratch (no allocs allowed -> __device__ globals)
__device__ float g_off[COFF * NPOS];            // offset conv output, [ch][pos]
__device__ float g_weff[8 * CIN * COFF * 8];    // parity-combined weights [par][c][o][j]
__device__ float g_wT[27 * CIN * COUT];         // main weights [tap][c][oc]
__device__ float g_xT[NCELL * CIN];             // x transposed [cell][c]
__device__ float g_scale[COUT];
__device__ float g_shift[COUT];

// ---------------------------------------------------------------------------
// K0a: transpose main conv weights to [tap][c][oc] (one-time, tiny).
// ---------------------------------------------------------------------------
__global__ void k_wT(const float* __restrict__ wmain) {
    int t = blockIdx.x * blockDim.x + threadIdx.x;
    if (t >= 27 * CIN * COUT) return;
    int oc  = t & 31;
    int c   = (t >> 5) & 63;
    int tap = t >> 11;
    g_wT[t] = wmain[(oc * CIN + c) * 27 + tap];
}

// K0b: transpose x to [cell][c] (for lane=channel gathers).
__global__ void k_xT(const float* __restrict__ x) {
    int t = blockIdx.x * blockDim.x + threadIdx.x;
    if (t >= NCELL * CIN) return;
    int c = t & 63, cell = t >> 6;
    g_xT[t] = x[c * NCELL + cell];
}

// ---------------------------------------------------------------------------
// K1: parity-combined effective weights [par][c][o][j].
// ---------------------------------------------------------------------------
__global__ void k_weff(const float* __restrict__ w_off) {
    int t = blockIdx.x * blockDim.x + threadIdx.x;
    if (t >= 8 * CIN * COFF * 8) return;
    int j  = t & 7;
    int o  = (t >> 3) % COFF;
    int c  = (t / (8 * COFF)) % CIN;
    int par = t / (8 * COFF * CIN);
    int pd = (par >> 2) & 1, ph = (par >> 1) & 1, pw = par & 1;
    int jd = (j >> 2) & 1,  jh = (j >> 1) & 1,  jw = j & 1;
    int sd = jd * (1 + pd), nd = (pd != jd) ? 2 : 1;
    int sh = jh * (1 + ph), nh = (ph != jh) ? 2 : 1;
    int sw = jw * (1 + pw), nw = (pw != jw) ? 2 : 1;
    const float* wb = w_off + (o * CIN + c) * 27;
    float s = 0.f;
    for (int a = 0; a < nd; a++)
        for (int bq = 0; bq < nh; bq++)
            for (int cc = 0; cc < nw; cc++)
                s += wb[(sd + a) * 9 + (sh + bq) * 3 + (sw + cc)];
    g_weff[t] = s;
}

// ---------------------------------------------------------------------------
// K2: offset conv (R3 structure). 3-way oc-split, direct __ldg weights.
// grid = 8 par x 32 tiles x 3 = 768, 128 threads.
// ---------------------------------------------------------------------------
__global__ void __launch_bounds__(128) k_offconv(const float* __restrict__ x,
                                                 const float* __restrict__ b_off) {
    int bid  = blockIdx.x;
    int par  = bid / 96;
    int rest = bid % 96;
    int tile = rest / 3;
    int osec = rest % 3;                      // 27 output channels each
    int q = tile * 128 + threadIdx.x;         // coarse linear index, 0..4095
    int qw = q & 15, qh = (q >> 4) & 15, qd = q >> 8;
    int pd = (par >> 2) & 1, ph = (par >> 1) & 1, pw = par & 1;

    const float* pj[8]; float msk[8];
    #pragma unroll
    for (int j = 0; j < 8; j++) {
        int cd = qd + pd - 1 + ((j >> 2) & 1);
        int ch = qh + ph - 1 + ((j >> 1) & 1);
        int cw = qw + pw - 1 + (j & 1);
        bool v = (unsigned)cd < 16u && (unsigned)ch < 16u && (unsigned)cw < 16u;
        pj[j]  = x + (v ? ((cd * 16 + ch) * 16 + cw) : 0);
        msk[j] = v ? 1.f : 0.f;
    }

    float acc[27];
    #pragma unroll
    for (int o = 0; o < 27; o++) acc[o] = 0.f;

    #pragma unroll 2
    for (int c = 0; c < CIN; c++) {
        float xv[8];
        #pragma unroll
        for (int j = 0; j < 8; j++) xv[j] = msk[j] * __ldg(pj[j] + c * NCELL);
        const float4* wr = (const float4*)(g_weff +
            ((size_t)(par * CIN + c) * COFF + osec * 27) * 8);
        #pragma unroll
        for (int o = 0; o < 27; o++) {
            float4 wa = __ldg(wr + o * 2);
            float4 wb2 = __ldg(wr + o * 2 + 1);
            acc[o] += xv[0]*wa.x + xv[1]*wa.y + xv[2]*wa.z + xv[3]*wa.w
                    + xv[4]*wb2.x + xv[5]*wb2.y + xv[6]*wb2.z + xv[7]*wb2.w;
        }
    }
    int df = 2*qd + pd, hf = 2*qh + ph, wf = 2*qw + pw;
    int p = (df * 32 + hf) * 32 + wf;
    #pragma unroll
    for (int o = 0; o < 27; o++)
        g_off[(osec * 27 + o) * NPOS + p] = acc[o] + b_off[osec * 27 + o];
}

// ---------------------------------------------------------------------------
// K3: two-phase deformable conv.
// Phase A (lane=channel): warps sample corners from g_xT[cell][c] with
//   contiguous 128B requests + corner dedup; write sm_samp[pos][c].
// Phase B (thread=pos x ch-quarter): contraction vs smem-staged weights.
// ---------------------------------------------------------------------------
__global__ void __launch_bounds__(256, 2) k_deform(const float* __restrict__ bmain,
                                                   float* __restrict__ out) {
    __shared__ __align__(16) float ws[CIN * COUT];  // per-tap weights [c][oc], 8 KB
    __shared__ float sm_samp[64 * 66];              // samp[pos][c] pad 66; also red
    int tid  = threadIdx.x;
    int wrp  = tid >> 5;
    int lane = tid & 31;
    int posi = tid & 63;
    int cs   = tid >> 6;                      // channel quarter 0..3 (phase B)

    float acc[COUT];
    #pragma unroll
    for (int i = 0; i < COUT; i++) acc[i] = 0.f;

    #pragma unroll 1
    for (int tap = 0; tap < 27; tap++) {
        int kd = tap / 9, kh = (tap / 3) % 3, kw = tap % 3;
        __syncthreads();

        // stage per-tap weights (contiguous 8KB)
        {
            const float4* src = (const float4*)(g_wT + tap * CIN * COUT);
            float4* dst = (float4*)ws;
            for (int i = tid; i < CIN * COUT / 4; i += 256) dst[i] = src[i];
        }

        // Phase A: 128 units = 64 pos x 2 ch-halves over 8 warps
        #pragma unroll 1
        for (int i = 0; i < 16; i++) {
            int unit = wrp * 16 + i;
            int pos  = unit >> 1;
            int half = unit & 1;
            int pp = blockIdx.x * 64 + pos;
            int pwf = pp & 31, phf = (pp >> 5) & 31, pdf = pp >> 10;

            float pdc = (float)(pdf + kd - 1) + __ldg(&g_off[(tap * 3 + 0) * NPOS + pp]);
            float phc = (float)(phf + kh - 1) + __ldg(&g_off[(tap * 3 + 1) * NPOS + pp]);
            float pwc = (float)(pwf + kw - 1) + __ldg(&g_off[(tap * 3 + 2) * NPOS + pp]);
            float fd0 = floorf(pdc), fh0 = floorf(phc), fw0 = floorf(pwc);
            int id0 = (int)fd0, ih0 = (int)fh0, iw0 = (int)fw0;
            float fd = pdc - fd0, fh = phc - fh0, fw = pwc - fw0;

            int cD[2], cH[2], cW[2]; float wD[2], wH[2], wW[2];
            cD[0] = id0 >> 1; cD[1] = (id0 + 1) >> 1;
            cH[0] = ih0 >> 1; cH[1] = (ih0 + 1) >> 1;
            cW[0] = iw0 >> 1; cW[1] = (iw0 + 1) >> 1;
            bool ed = !(id0 & 1), eh = !(ih0 & 1), ew = !(iw0 & 1);
            wD[0] = ed ? 1.f : 1.f - fd;  wD[1] = ed ? 0.f : fd;
            wH[0] = eh ? 1.f : 1.f - fh;  wH[1] = eh ? 0.f : fh;
            wW[0] = ew ? 1.f : 1.f - fw;  wW[1] = ew ? 0.f : fw;
            if ((unsigned)cD[0] >= 16u) wD[0] = 0.f;
            if ((unsigned)cD[1] >= 16u) wD[1] = 0.f;
            if ((unsigned)cH[0] >= 16u) wH[0] = 0.f;
            if ((unsigned)cH[1] >= 16u) wH[1] = 0.f;
            if ((unsigned)cW[0] >= 16u) wW[0] = 0.f;
            if ((unsigned)cW[1] >= 16u) wW[1] = 0.f;

            const float* xb = g_xT + half * 32 + lane;
            float sv = 0.f;
            #pragma unroll
            for (int jd = 0; jd < 2; jd++)
            #pragma unroll
            for (int jh = 0; jh < 2; jh++)
            #pragma unroll
            for (int jw = 0; jw < 2; jw++) {
                float wj = wD[jd] * wH[jh] * wW[jw];
                if (wj != 0.f) {   // uniform across warp -> no divergence
                    int cell = (cD[jd] * 16 + cH[jh]) * 16 + cW[jw];
                    sv += wj * __ldg(xb + cell * CIN);
                }
            }
            sm_samp[pos * 66 + half * 32 + lane] = sv;
        }
        __syncthreads();

        // Phase B: contraction acc[32] += samp[c] * W[c][oc]
        const float* srow = sm_samp + posi * 66 + cs * 16;
        #pragma unroll
        for (int cc = 0; cc < 16; cc++) {
            float v = srow[cc];
            const float4* wrow = (const float4*)(ws + (cs * 16 + cc) * 32);
            #pragma unroll
            for (int k = 0; k < 8; k++) {
                float4 wv = wrow[k];
                acc[k*4+0] += v * wv.x;
                acc[k*4+1] += v * wv.y;
                acc[k*4+2] += v * wv.z;
                acc[k*4+3] += v * wv.w;
            }
        }
    }

    // tree-reduce across the 4 channel quarters (reuse sm_samp as red)
    float* red = sm_samp;   // need 2*64*33 = 4224 <= 64*66 = 4224
    int p = blockIdx.x * 64 + posi;
    __syncthreads();
    if (cs >= 2) {
        float* dst = red + ((cs - 2) * 64 + posi) * 33;
        #pragma unroll
        for (int oc = 0; oc < COUT; oc++) dst[oc] = acc[oc];
    }
    __syncthreads();
    if (cs < 2) {
        const float* src = red + (cs * 64 + posi) * 33;
        #pragma unroll
        for (int oc = 0; oc < COUT; oc++) acc[oc] += src[oc];
    }
    __syncthreads();
    if (cs == 1) {
        float* dst = red + posi * 33;
        #pragma unroll
        for (int oc = 0; oc < COUT; oc++) dst[oc] = acc[oc];
    }
    __syncthreads();
    if (cs == 0) {
        const float* src = red + posi * 33;
        #pragma unroll
        for (int oc = 0; oc < COUT; oc++)
            out[oc * NPOS + p] = acc[oc] + src[oc] + bmain[oc];
    }
}

// ---------------------------------------------------------------------------
// K4a: per-channel mean/var -> scale/shift.  K4b: normalize + ReLU in place.
// ---------------------------------------------------------------------------
__global__ void __launch_bounds__(1024) k_bnstat(const float* __restrict__ out,
                                                 const float* __restrict__ gamma,
                                                 const float* __restrict__ beta) {
    __shared__ float ssum[1024], ssq[1024];
    int ch = blockIdx.x;
    const float* base = out + ch * NPOS;
    float s = 0.f, sq = 0.f;
    for (int i = threadIdx.x; i < NPOS; i += 1024) {
        float v = base[i];
        s += v; sq += v * v;
    }
    ssum[threadIdx.x] = s; ssq[threadIdx.x] = sq;
    __syncthreads();
    for (int st = 512; st > 0; st >>= 1) {
        if (threadIdx.x < st) {
            ssum[threadIdx.x] += ssum[threadIdx.x + st];
            ssq[threadIdx.x]  += ssq[threadIdx.x + st];
        }
        __syncthreads();
    }
    if (threadIdx.x == 0) {
        float mean = ssum[0] * (1.f / (float)NPOS);
        float var  = ssq[0] * (1.f / (float)NPOS) - mean * mean;
        float inv  = rsqrtf(var + 1e-5f);
        float a = gamma[ch] * inv;
        g_scale[ch] = a;
        g_shift[ch] = beta[ch] - mean * a;
    }
}

__global__ void k_bnapply(float* __restrict__ out) {
    int idx = blockIdx.x * 256 + threadIdx.x;
    int ch = idx >> 15;
    float v = out[idx] * g_scale[ch] + g_shift[ch];
    out[idx] = fmaxf(v, 0.f);
}

extern "C" void kernel_launch(void* const* d_in, const int* in_sizes, int n_in,
                              void* d_out, int out_size) {
    const float* x     = (const float*)d_in[0];   // (1,64,16,16,16)
    const float* w_off = (const float*)d_in[1];   // (81,64,3,3,3)
    const float* b_off = (const float*)d_in[2];   // (81,)
    const float* w     = (const float*)d_in[3];   // (32,64,3,3,3)
    const float* b     = (const float*)d_in[4];   // (32,)
    const float* gamma = (const float*)d_in[5];   // (32,)
    const float* beta  = (const float*)d_in[6];   // (32,)
    float* out = (float*)d_out;                   // (1,32,32,32,32)

    k_wT<<<(27 * CIN * COUT + 255) / 256, 256>>>(w);
    k_xT<<<(NCELL * CIN) / 256, 256>>>(x);
    k_weff<<<(8 * CIN * COFF * 8) / 256, 256>>>(w_off);
    k_offconv<<<768, 128>>>(x, b_off);
    k_deform<<<512, 256>>>(b, out);
    k_bnstat<<<COUT, 1024>>>(out, gamma, beta);
    k_bnapply<<<4096, 256>>>(out);
}

// round 10
// speedup vs baseline: 2.1696x; 2.1696x over previous
#include <cuda_runtime.h>
#include <math.h>

#define NPOS 32768      // 32^3 fine positions
#define NCELL 4096      // 16^3 coarse cells
#define CIN 64
#define COFF 81         // 3 * 27 offset channels
#define COUT 32
#define CCHUNK 16

// Scratch (no allocs allowed -> __device__ globals)
__device__ float g_off[COFF * NPOS];            // offset conv output, [ch][pos]
__device__ float g_weff[8 * CIN * COFF * 8];    // parity-combined weights [par][c][o][j]
__device__ float g_wT[27 * CIN * COUT];         // main weights [tap][c][oc]
__device__ float g_scale[COUT];
__device__ float g_shift[COUT];

// ---------------------------------------------------------------------------
// K0: transpose main conv weights to [tap][c][oc] (one-time, tiny).
// ---------------------------------------------------------------------------
__global__ void k_wT(const float* __restrict__ wmain) {
    int t = blockIdx.x * blockDim.x + threadIdx.x;
    if (t >= 27 * CIN * COUT) return;
    int oc  = t & 31;
    int c   = (t >> 5) & 63;
    int tap = t >> 11;
    g_wT[t] = wmain[(oc * CIN + c) * 27 + tap];
}

// ---------------------------------------------------------------------------
// K1: parity-combined effective weights [par][c][o][j] (2x nearest upsample
// + 3^3 conv == per-parity 8-tap conv on the coarse grid).
// ---------------------------------------------------------------------------
__global__ void k_weff(const float* __restrict__ w_off) {
    int t = blockIdx.x * blockDim.x + threadIdx.x;
    if (t >= 8 * CIN * COFF * 8) return;
    int j  = t & 7;
    int o  = (t >> 3) % COFF;
    int c  = (t / (8 * COFF)) % CIN;
    int par = t / (8 * COFF * CIN);
    int pd = (par >> 2) & 1, ph = (par >> 1) & 1, pw = par & 1;
    int jd = (j >> 2) & 1,  jh = (j >> 1) & 1,  jw = j & 1;
    int sd = jd * (1 + pd), nd = (pd != jd) ? 2 : 1;
    int sh = jh * (1 + ph), nh = (ph != jh) ? 2 : 1;
    int sw = jw * (1 + pw), nw = (pw != jw) ? 2 : 1;
    const float* wb = w_off + (o * CIN + c) * 27;
    float s = 0.f;
    for (int a = 0; a < nd; a++)
        for (int bq = 0; bq < nh; bq++)
            for (int cc = 0; cc < nw; cc++)
                s += wb[(sd + a) * 9 + (sh + bq) * 3 + (sw + cc)];
    g_weff[t] = s;   // layout [par][c][o][j]
}

// ---------------------------------------------------------------------------
// K2: offset conv — R1/R3 original (measured best ~140us). Block = 128
// coarse positions of one parity; smem-staged weight chunks; acc[81].
// ---------------------------------------------------------------------------
__global__ void __launch_bounds__(128) k_offconv(const float* __restrict__ x,
                                                 const float* __restrict__ b_off) {
    __shared__ float sw[CCHUNK * COFF * 8];   // 41472 B
    int par  = blockIdx.x >> 5;
    int tile = blockIdx.x & 31;
    int q = tile * 128 + threadIdx.x;         // coarse linear index, 0..4095
    int qw = q & 15, qh = (q >> 4) & 15, qd = q >> 8;
    int pd = (par >> 2) & 1, ph = (par >> 1) & 1, pw = par & 1;

    int sp[8]; float msk[8];
    #pragma unroll
    for (int j = 0; j < 8; j++) {
        int cd = qd + pd - 1 + ((j >> 2) & 1);
        int ch = qh + ph - 1 + ((j >> 1) & 1);
        int cw = qw + pw - 1 + (j & 1);
        bool v = (unsigned)cd < 16u && (unsigned)ch < 16u && (unsigned)cw < 16u;
        sp[j]  = v ? ((cd * 16 + ch) * 16 + cw) : 0;
        msk[j] = v ? 1.f : 0.f;
    }

    float acc[COFF];
    #pragma unroll
    for (int o = 0; o < COFF; o++) acc[o] = 0.f;

    #pragma unroll 1
    for (int c0 = 0; c0 < CIN; c0 += CCHUNK) {
        __syncthreads();
        const float* gsrc = g_weff + ((size_t)(par * CIN + c0) * COFF) * 8;
        for (int i = threadIdx.x; i < CCHUNK * COFF * 8; i += 128)
            sw[i] = gsrc[i];
        __syncthreads();
        #pragma unroll 1
        for (int cc = 0; cc < CCHUNK; cc++) {
            const float* xb = x + (c0 + cc) * NCELL;
            float xv[8];
            #pragma unroll
            for (int j = 0; j < 8; j++) xv[j] = msk[j] * __ldg(&xb[sp[j]]);
            const float4* wrow = (const float4*)(sw + cc * COFF * 8);
            #pragma unroll
            for (int o = 0; o < COFF; o++) {
                float4 wa = wrow[o * 2];
                float4 wb2 = wrow[o * 2 + 1];
                acc[o] += xv[0]*wa.x + xv[1]*wa.y + xv[2]*wa.z + xv[3]*wa.w
                        + xv[4]*wb2.x + xv[5]*wb2.y + xv[6]*wb2.z + xv[7]*wb2.w;
            }
        }
    }
    int df = 2*qd + pd, hf = 2*qh + ph, wf = 2*qw + pw;
    int p = (df * 32 + hf) * 32 + wf;
    #pragma unroll 1
    for (int o = 0; o < COFF; o++)
        g_off[o * NPOS + p] = acc[o] + b_off[o];
}

// ---------------------------------------------------------------------------
// K3: deformable sampling — R7 version (measured 232us). Corner-dedup:
// trilinear on the upsampled grid collapses per axis; zero-weight corners
// (duplicates + OOB) skipped. smem weight staging, 4-way channel split.
// ---------------------------------------------------------------------------
__global__ void __launch_bounds__(256, 2) k_deform(const float* __restrict__ x,
                                                   const float* __restrict__ bmain,
                                                   float* __restrict__ out) {
    __shared__ __align__(16) float ws[CIN * COUT];  // per-tap weights [c][oc], 8 KB
    __shared__ float red[2 * 64 * 33];              // reduction, padded
    int tid  = threadIdx.x;
    int posi = tid & 63;
    int cs   = tid >> 6;                      // channel quarter 0..3
    int p = blockIdx.x * 64 + posi;
    int wf = p & 31, hf = (p >> 5) & 31, df = p >> 10;

    float acc[COUT];
    #pragma unroll
    for (int i = 0; i < COUT; i++) acc[i] = 0.f;

    const float* xbase = x + cs * 16 * NCELL;

    #pragma unroll 1
    for (int tap = 0; tap < 27; tap++) {
        __syncthreads();
        {   // coalesced 8KB copy: g_wT[tap] is contiguous [c][oc]
            const float4* src = (const float4*)(g_wT + tap * CIN * COUT);
            float4* dst = (float4*)ws;
            for (int i = tid; i < CIN * COUT / 4; i += 256) dst[i] = src[i];
        }
        __syncthreads();

        int kd = tap / 9, kh = (tap / 3) % 3, kw = tap % 3;
        float pdc = (float)(df + kd - 1) + __ldg(&g_off[(tap * 3 + 0) * NPOS + p]);
        float phc = (float)(hf + kh - 1) + __ldg(&g_off[(tap * 3 + 1) * NPOS + p]);
        float pwc = (float)(wf + kw - 1) + __ldg(&g_off[(tap * 3 + 2) * NPOS + p]);
        float fd0 = floorf(pdc), fh0 = floorf(phc), fw0 = floorf(pwc);
        int id0 = (int)fd0, ih0 = (int)fh0, iw0 = (int)fw0;
        float fd = pdc - fd0, fh = phc - fh0, fw = pwc - fw0;

        // per-axis coarse slots + folded weights (even base -> single slot)
        int cD[2], cH[2], cW[2]; float wD[2], wH[2], wW[2];
        cD[0] = id0 >> 1; cD[1] = (id0 + 1) >> 1;
        cH[0] = ih0 >> 1; cH[1] = (ih0 + 1) >> 1;
        cW[0] = iw0 >> 1; cW[1] = (iw0 + 1) >> 1;
        bool ed = !(id0 & 1), eh = !(ih0 & 1), ew = !(iw0 & 1);
        wD[0] = ed ? 1.f : 1.f - fd;  wD[1] = ed ? 0.f : fd;
        wH[0] = eh ? 1.f : 1.f - fh;  wH[1] = eh ? 0.f : fh;
        wW[0] = ew ? 1.f : 1.f - fw;  wW[1] = ew ? 0.f : fw;
        if ((unsigned)cD[0] >= 16u) wD[0] = 0.f;
        if ((unsigned)cD[1] >= 16u) wD[1] = 0.f;
        if ((unsigned)cH[0] >= 16u) wH[0] = 0.f;
        if ((unsigned)cH[1] >= 16u) wH[1] = 0.f;
        if ((unsigned)cW[0] >= 16u) wW[0] = 0.f;
        if ((unsigned)cW[1] >= 16u) wW[1] = 0.f;

        float samp[16];
        #pragma unroll
        for (int i = 0; i < 16; i++) samp[i] = 0.f;

        #pragma unroll
        for (int jd = 0; jd < 2; jd++)
        #pragma unroll
        for (int jh = 0; jh < 2; jh++)
        #pragma unroll
        for (int jw = 0; jw < 2; jw++) {
            float wj = wD[jd] * wH[jh] * wW[jw];
            if (wj != 0.f) {
                const float* xb = xbase + ((cD[jd] * 16 + cH[jh]) * 16 + cW[jw]);
                #pragma unroll
                for (int cc = 0; cc < 16; cc++)
                    samp[cc] += wj * __ldg(xb + cc * NCELL);
            }
        }

        // contraction: acc[32] += samp[16c] * W[c][oc]
        #pragma unroll
        for (int cc = 0; cc < 16; cc++) {
            float v = samp[cc];
            const float4* wrow = (const float4*)(ws + (cs * 16 + cc) * 32);
            #pragma unroll
            for (int k = 0; k < 8; k++) {
                float4 wv = wrow[k];
                acc[k*4+0] += v * wv.x;
                acc[k*4+1] += v * wv.y;
                acc[k*4+2] += v * wv.z;
                acc[k*4+3] += v * wv.w;
            }
        }
    }

    // tree-reduce across the 4 channel quarters
    __syncthreads();
    if (cs >= 2) {
        float* dst = red + ((cs - 2) * 64 + posi) * 33;
        #pragma unroll
        for (int oc = 0; oc < COUT; oc++) dst[oc] = acc[oc];
    }
    __syncthreads();
    if (cs < 2) {
        const float* src = red + (cs * 64 + posi) * 33;
        #pragma unroll
        for (int oc = 0; oc < COUT; oc++) acc[oc] += src[oc];
    }
    __syncthreads();
    if (cs == 1) {
        float* dst = red + posi * 33;
        #pragma unroll
        for (int oc = 0; oc < COUT; oc++) dst[oc] = acc[oc];
    }
    __syncthreads();
    if (cs == 0) {
        const float* src = red + posi * 33;
        #pragma unroll
        for (int oc = 0; oc < COUT; oc++)
            out[oc * NPOS + p] = acc[oc] + src[oc] + bmain[oc];
    }
}

// ---------------------------------------------------------------------------
// K4a: per-channel mean/var -> scale/shift.  K4b: normalize + ReLU in place.
// ---------------------------------------------------------------------------
__global__ void __launch_bounds__(1024) k_bnstat(const float* __restrict__ out,
                                                 const float* __restrict__ gamma,
                                                 const float* __restrict__ beta) {
    __shared__ float ssum[1024], ssq[1024];
    int ch = blockIdx.x;
    const float* base = out + ch * NPOS;
    float s = 0.f, sq = 0.f;
    for (int i = threadIdx.x; i < NPOS; i += 1024) {
        float v = base[i];
        s += v; sq += v * v;
    }
    ssum[threadIdx.x] = s; ssq[threadIdx.x] = sq;
    __syncthreads();
    for (int st = 512; st > 0; st >>= 1) {
        if (threadIdx.x < st) {
            ssum[threadIdx.x] += ssum[threadIdx.x + st];
            ssq[threadIdx.x]  += ssq[threadIdx.x + st];
        }
        __syncthreads();
    }
    if (threadIdx.x == 0) {
        float mean = ssum[0] * (1.f / (float)NPOS);
        float var  = ssq[0] * (1.f / (float)NPOS) - mean * mean;
        float inv  = rsqrtf(var + 1e-5f);
        float a = gamma[ch] * inv;
        g_scale[ch] = a;
        g_shift[ch] = beta[ch] - mean * a;
    }
}

__global__ void k_bnapply(float* __restrict__ out) {
    int idx = blockIdx.x * 256 + threadIdx.x;
    int ch = idx >> 15;
    float v = out[idx] * g_scale[ch] + g_shift[ch];
    out[idx] = fmaxf(v, 0.f);
}

extern "C" void kernel_launch(void* const* d_in, const int* in_sizes, int n_in,
                              void* d_out, int out_size) {
    const float* x     = (const float*)d_in[0];   // (1,64,16,16,16)
    const float* w_off = (const float*)d_in[1];   // (81,64,3,3,3)
    const float* b_off = (const float*)d_in[2];   // (81,)
    const float* w     = (const float*)d_in[3];   // (32,64,3,3,3)
    const float* b     = (const float*)d_in[4];   // (32,)
    const float* gamma = (const float*)d_in[5];   // (32,)
    const float* beta  = (const float*)d_in[6];   // (32,)
    float* out = (float*)d_out;                   // (1,32,32,32,32)

    k_wT<<<(27 * CIN * COUT + 255) / 256, 256>>>(w);
    k_weff<<<(8 * CIN * COFF * 8) / 256, 256>>>(w_off);
    k_offconv<<<256, 128>>>(x, b_off);
    k_deform<<<512, 256>>>(x, b, out);
    k_bnstat<<<COUT, 1024>>>(out, gamma, beta);
    k_bnapply<<<4096, 256>>>(out);
}

// round 11
// speedup vs baseline: 2.7977x; 1.2895x over previous
#include <cuda_runtime.h>
#include <math.h>

#define NPOS 32768      // 32^3 fine positions
#define NCELL 4096      // 16^3 coarse cells
#define CIN 64
#define COFF 81         // 3 * 27 offset channels
#define COUT 32
#define CCHUNK 16

// Scratch (no allocs allowed -> __device__ globals)
__device__ float g_off[COFF * NPOS];            // offset conv output, [ch][pos]
__device__ float g_weff[8 * CIN * COFF * 8];    // parity-combined weights [par][c][o][j]
__device__ float g_wT[27 * CIN * COUT];         // main weights [tap][c][oc]
__device__ float g_scale[COUT];
__device__ float g_shift[COUT];

// ---------------------------------------------------------------------------
// K0: transpose main conv weights to [tap][c][oc] (one-time, tiny).
// ---------------------------------------------------------------------------
__global__ void k_wT(const float* __restrict__ wmain) {
    int t = blockIdx.x * blockDim.x + threadIdx.x;
    if (t >= 27 * CIN * COUT) return;
    int oc  = t & 31;
    int c   = (t >> 5) & 63;
    int tap = t >> 11;
    g_wT[t] = wmain[(oc * CIN + c) * 27 + tap];
}

// ---------------------------------------------------------------------------
// K1: parity-combined effective weights [par][c][o][j].
// ---------------------------------------------------------------------------
__global__ void k_weff(const float* __restrict__ w_off) {
    int t = blockIdx.x * blockDim.x + threadIdx.x;
    if (t >= 8 * CIN * COFF * 8) return;
    int j  = t & 7;
    int o  = (t >> 3) % COFF;
    int c  = (t / (8 * COFF)) % CIN;
    int par = t / (8 * COFF * CIN);
    int pd = (par >> 2) & 1, ph = (par >> 1) & 1, pw = par & 1;
    int jd = (j >> 2) & 1,  jh = (j >> 1) & 1,  jw = j & 1;
    int sd = jd * (1 + pd), nd = (pd != jd) ? 2 : 1;
    int sh = jh * (1 + ph), nh = (ph != jh) ? 2 : 1;
    int sw = jw * (1 + pw), nw = (pw != jw) ? 2 : 1;
    const float* wb = w_off + (o * CIN + c) * 27;
    float s = 0.f;
    for (int a = 0; a < nd; a++)
        for (int bq = 0; bq < nh; bq++)
            for (int cc = 0; cc < nw; cc++)
                s += wb[(sd + a) * 9 + (sh + bq) * 3 + (sw + cc)];
    g_weff[t] = s;   // layout [par][c][o][j]
}

// ---------------------------------------------------------------------------
// K2: offset conv, 2-position register blocking + 3-way osec split.
// grid = 8 par x 16 tiles x 3 osec = 384 blocks, 128 threads.
// Thread handles coarse positions q and q+128; each smem weight read
// feeds FMAs for both -> smem traffic per FMA halved.
// ---------------------------------------------------------------------------
__global__ void __launch_bounds__(128) k_offconv(const float* __restrict__ x,
                                                 const float* __restrict__ b_off) {
    __shared__ float sw[CCHUNK * 27 * 8];     // 13.8 KB
    int bid  = blockIdx.x;
    int par  = bid / 48;
    int rest = bid % 48;
    int tile = rest / 3;
    int osec = rest % 3;
    int ti   = threadIdx.x;
    int q0 = tile * 256 + ti;                 // and q0 + 128
    int pd = (par >> 2) & 1, ph = (par >> 1) & 1, pw = par & 1;

    int sp[2][8]; float msk[2][8];
    #pragma unroll
    for (int s = 0; s < 2; s++) {
        int q = q0 + s * 128;
        int qw = q & 15, qh = (q >> 4) & 15, qd = q >> 8;
        #pragma unroll
        for (int j = 0; j < 8; j++) {
            int cd = qd + pd - 1 + ((j >> 2) & 1);
            int ch = qh + ph - 1 + ((j >> 1) & 1);
            int cw = qw + pw - 1 + (j & 1);
            bool v = (unsigned)cd < 16u && (unsigned)ch < 16u && (unsigned)cw < 16u;
            sp[s][j]  = v ? ((cd * 16 + ch) * 16 + cw) : 0;
            msk[s][j] = v ? 1.f : 0.f;
        }
    }

    float acc[2][27];
    #pragma unroll
    for (int s = 0; s < 2; s++)
        #pragma unroll
        for (int o = 0; o < 27; o++) acc[s][o] = 0.f;

    #pragma unroll 1
    for (int c0 = 0; c0 < CIN; c0 += CCHUNK) {
        __syncthreads();
        for (int i = ti; i < CCHUNK * 27 * 8; i += 128) {
            int cc = i / (27 * 8);
            int ii = i % (27 * 8);
            sw[i] = g_weff[((size_t)(par * CIN + c0 + cc) * COFF + osec * 27) * 8 + ii];
        }
        __syncthreads();
        #pragma unroll 1
        for (int cc = 0; cc < CCHUNK; cc++) {
            const float* xb = x + (c0 + cc) * NCELL;
            float xv[2][8];
            #pragma unroll
            for (int s = 0; s < 2; s++)
                #pragma unroll
                for (int j = 0; j < 8; j++)
                    xv[s][j] = msk[s][j] * __ldg(&xb[sp[s][j]]);
            const float4* wrow = (const float4*)(sw + cc * 27 * 8);
            #pragma unroll
            for (int o = 0; o < 27; o++) {
                float4 wa = wrow[o * 2];
                float4 wb2 = wrow[o * 2 + 1];
                acc[0][o] += xv[0][0]*wa.x + xv[0][1]*wa.y + xv[0][2]*wa.z + xv[0][3]*wa.w
                           + xv[0][4]*wb2.x + xv[0][5]*wb2.y + xv[0][6]*wb2.z + xv[0][7]*wb2.w;
                acc[1][o] += xv[1][0]*wa.x + xv[1][1]*wa.y + xv[1][2]*wa.z + xv[1][3]*wa.w
                           + xv[1][4]*wb2.x + xv[1][5]*wb2.y + xv[1][6]*wb2.z + xv[1][7]*wb2.w;
            }
        }
    }
    #pragma unroll
    for (int s = 0; s < 2; s++) {
        int q = q0 + s * 128;
        int qw = q & 15, qh = (q >> 4) & 15, qd = q >> 8;
        int df = 2*qd + pd, hf = 2*qh + ph, wf = 2*qw + pw;
        int p = (df * 32 + hf) * 32 + wf;
        #pragma unroll
        for (int o = 0; o < 27; o++)
            g_off[(osec * 27 + o) * NPOS + p] = acc[s][o] + b_off[osec * 27 + o];
    }
}

// ---------------------------------------------------------------------------
// K3 helpers
// ---------------------------------------------------------------------------
__device__ __forceinline__ void sample16(const float* __restrict__ xbase,
                                         int tap, int kd, int kh, int kw,
                                         int p, float* samp) {
    int wf = p & 31, hf = (p >> 5) & 31, df = p >> 10;
    float pdc = (float)(df + kd - 1) + __ldg(&g_off[(tap * 3 + 0) * NPOS + p]);
    float phc = (float)(hf + kh - 1) + __ldg(&g_off[(tap * 3 + 1) * NPOS + p]);
    float pwc = (float)(wf + kw - 1) + __ldg(&g_off[(tap * 3 + 2) * NPOS + p]);
    float fd0 = floorf(pdc), fh0 = floorf(phc), fw0 = floorf(pwc);
    int id0 = (int)fd0, ih0 = (int)fh0, iw0 = (int)fw0;
    float fd = pdc - fd0, fh = phc - fh0, fw = pwc - fw0;

    int cD[2], cH[2], cW[2]; float wD[2], wH[2], wW[2];
    cD[0] = id0 >> 1; cD[1] = (id0 + 1) >> 1;
    cH[0] = ih0 >> 1; cH[1] = (ih0 + 1) >> 1;
    cW[0] = iw0 >> 1; cW[1] = (iw0 + 1) >> 1;
    bool ed = !(id0 & 1), eh = !(ih0 & 1), ew = !(iw0 & 1);
    wD[0] = ed ? 1.f : 1.f - fd;  wD[1] = ed ? 0.f : fd;
    wH[0] = eh ? 1.f : 1.f - fh;  wH[1] = eh ? 0.f : fh;
    wW[0] = ew ? 1.f : 1.f - fw;  wW[1] = ew ? 0.f : fw;
    if ((unsigned)cD[0] >= 16u) wD[0] = 0.f;
    if ((unsigned)cD[1] >= 16u) wD[1] = 0.f;
    if ((unsigned)cH[0] >= 16u) wH[0] = 0.f;
    if ((unsigned)cH[1] >= 16u) wH[1] = 0.f;
    if ((unsigned)cW[0] >= 16u) wW[0] = 0.f;
    if ((unsigned)cW[1] >= 16u) wW[1] = 0.f;

    #pragma unroll
    for (int i = 0; i < 16; i++) samp[i] = 0.f;

    #pragma unroll
    for (int jd = 0; jd < 2; jd++)
    #pragma unroll
    for (int jh = 0; jh < 2; jh++)
    #pragma unroll
    for (int jw = 0; jw < 2; jw++) {
        float wj = wD[jd] * wH[jh] * wW[jw];
        if (wj != 0.f) {
            const float* xb = xbase + ((cD[jd] * 16 + cH[jh]) * 16 + cW[jw]);
            #pragma unroll
            for (int cc = 0; cc < 16; cc++)
                samp[cc] += wj * __ldg(xb + cc * NCELL);
        }
    }
}

__device__ __forceinline__ void reduce_write(float* red, const float* acc,
                                             int cs, int posi, int p,
                                             const float* __restrict__ bmain,
                                             float* __restrict__ out) {
    __syncthreads();
    if (cs >= 2) {
        float* dst = red + ((cs - 2) * 64 + posi) * 33;
        #pragma unroll
        for (int oc = 0; oc < COUT; oc++) dst[oc] = acc[oc];
    }
    __syncthreads();
    float a2[COUT];
    if (cs < 2) {
        const float* src = red + (cs * 64 + posi) * 33;
        #pragma unroll
        for (int oc = 0; oc < COUT; oc++) a2[oc] = acc[oc] + src[oc];
    }
    __syncthreads();
    if (cs == 1) {
        float* dst = red + posi * 33;
        #pragma unroll
        for (int oc = 0; oc < COUT; oc++) dst[oc] = a2[oc];
    }
    __syncthreads();
    if (cs == 0) {
        const float* src = red + posi * 33;
        #pragma unroll
        for (int oc = 0; oc < COUT; oc++)
            out[oc * NPOS + p] = a2[oc] + src[oc] + bmain[oc];
    }
}

// ---------------------------------------------------------------------------
// K3: deformable conv, 2-position register blocking. Thread handles p and
// p+64 (same coalescing class); one smem weight pass feeds both acc sets.
// Block = 128 positions x 4 channel quarters; grid = 256.
// ---------------------------------------------------------------------------
__global__ void __launch_bounds__(256, 2) k_deform(const float* __restrict__ x,
                                                   const float* __restrict__ bmain,
                                                   float* __restrict__ out) {
    __shared__ __align__(16) float ws[CIN * COUT];  // per-tap weights [c][oc], 8 KB
    __shared__ float red[2 * 64 * 33];              // reduction, padded
    int tid  = threadIdx.x;
    int posi = tid & 63;
    int cs   = tid >> 6;                      // channel quarter 0..3
    int p0 = blockIdx.x * 128 + posi;         // and p0 + 64

    float acc0[COUT], acc1[COUT];
    #pragma unroll
    for (int i = 0; i < COUT; i++) { acc0[i] = 0.f; acc1[i] = 0.f; }

    const float* xbase = x + cs * 16 * NCELL;

    #pragma unroll 1
    for (int tap = 0; tap < 27; tap++) {
        __syncthreads();
        {   // coalesced 8KB copy
            const float4* src = (const float4*)(g_wT + tap * CIN * COUT);
            float4* dst = (float4*)ws;
            for (int i = tid; i < CIN * COUT / 4; i += 256) dst[i] = src[i];
        }
        __syncthreads();

        int kd = tap / 9, kh = (tap / 3) % 3, kw = tap % 3;
        float samp0[16], samp1[16];
        sample16(xbase, tap, kd, kh, kw, p0,      samp0);
        sample16(xbase, tap, kd, kh, kw, p0 + 64, samp1);

        #pragma unroll
        for (int cc = 0; cc < 16; cc++) {
            float v0 = samp0[cc], v1 = samp1[cc];
            const float4* wrow = (const float4*)(ws + (cs * 16 + cc) * 32);
            #pragma unroll
            for (int k = 0; k < 8; k++) {
                float4 wv = wrow[k];
                acc0[k*4+0] += v0 * wv.x;  acc1[k*4+0] += v1 * wv.x;
                acc0[k*4+1] += v0 * wv.y;  acc1[k*4+1] += v1 * wv.y;
                acc0[k*4+2] += v0 * wv.z;  acc1[k*4+2] += v1 * wv.z;
                acc0[k*4+3] += v0 * wv.w;  acc1[k*4+3] += v1 * wv.w;
            }
        }
    }

    reduce_write(red, acc0, cs, posi, p0,      bmain, out);
    reduce_write(red, acc1, cs, posi, p0 + 64, bmain, out);
}

// ---------------------------------------------------------------------------
// K4a: per-channel mean/var -> scale/shift.  K4b: normalize + ReLU in place.
// ---------------------------------------------------------------------------
__global__ void __launch_bounds__(1024) k_bnstat(const float* __restrict__ out,
                                                 const float* __restrict__ gamma,
                                                 const float* __restrict__ beta) {
    __shared__ float ssum[1024], ssq[1024];
    int ch = blockIdx.x;
    const float* base = out + ch * NPOS;
    float s = 0.f, sq = 0.f;
    for (int i = threadIdx.x; i < NPOS; i += 1024) {
        float v = base[i];
        s += v; sq += v * v;
    }
    ssum[threadIdx.x] = s; ssq[threadIdx.x] = sq;
    __syncthreads();
    for (int st = 512; st > 0; st >>= 1) {
        if (threadIdx.x < st) {
            ssum[threadIdx.x] += ssum[threadIdx.x + st];
            ssq[threadIdx.x]  += ssq[threadIdx.x + st];
        }
        __syncthreads();
    }
    if (threadIdx.x == 0) {
        float mean = ssum[0] * (1.f / (float)NPOS);
        float var  = ssq[0] * (1.f / (float)NPOS) - mean * mean;
        float inv  = rsqrtf(var + 1e-5f);
        float a = gamma[ch] * inv;
        g_scale[ch] = a;
        g_shift[ch] = beta[ch] - mean * a;
    }
}

__global__ void k_bnapply(float* __restrict__ out) {
    int idx = blockIdx.x * 256 + threadIdx.x;
    int ch = idx >> 15;
    float v = out[idx] * g_scale[ch] + g_shift[ch];
    out[idx] = fmaxf(v, 0.f);
}

extern "C" void kernel_launch(void* const* d_in, const int* in_sizes, int n_in,
                              void* d_out, int out_size) {
    const float* x     = (const float*)d_in[0];   // (1,64,16,16,16)
    const float* w_off = (const float*)d_in[1];   // (81,64,3,3,3)
    const float* b_off = (const float*)d_in[2];   // (81,)
    const float* w     = (const float*)d_in[3];   // (32,64,3,3,3)
    const float* b     = (const float*)d_in[4];   // (32,)
    const float* gamma = (const float*)d_in[5];   // (32,)
    const float* beta  = (const float*)d_in[6];   // (32,)
    float* out = (float*)d_out;                   // (1,32,32,32,32)

    k_wT<<<(27 * CIN * COUT + 255) / 256, 256>>>(w);
    k_weff<<<(8 * CIN * COFF * 8) / 256, 256>>>(w_off);
    k_offconv<<<384, 128>>>(x, b_off);
    k_deform<<<256, 256>>>(x, b, out);
    k_bnstat<<<COUT, 1024>>>(out, gamma, beta);
    k_bnapply<<<4096, 256>>>(out);
}

// round 12
// speedup vs baseline: 2.9544x; 1.0560x over previous
#include <cuda_runtime.h>
#include <math.h>

#define NPOS 32768      // 32^3 fine positions
#define NCELL 4096      // 16^3 coarse cells
#define CIN 64
#define COFF 81         // 3 * 27 offset channels
#define COUT 32
#define CCHUNK 16
#define OPAD 84         // 3 sections x 28 (27 padded for f32x2 pairs)

// Scratch (no allocs allowed -> __device__ globals)
__device__ float g_off[COFF * NPOS];            // offset conv output, [ch][pos]
__device__ float g_weff[8 * CIN * 8 * OPAD];    // [par][c][j][osec*28+oo]
__device__ float g_wT[27 * CIN * COUT];         // main weights [tap][c][oc]
__device__ float g_scale[COUT];
__device__ float g_shift[COUT];

// ---- packed f32x2 helpers -------------------------------------------------
__device__ __forceinline__ unsigned long long pack2(float v) {
    unsigned long long r;
    unsigned u = __float_as_uint(v);
    asm("mov.b64 %0, {%1, %1};" : "=l"(r) : "r"(u));
    return r;
}
__device__ __forceinline__ void fma2(unsigned long long& d,
                                     unsigned long long a,
                                     unsigned long long b) {
    asm("fma.rn.f32x2 %0, %1, %2, %0;" : "+l"(d) : "l"(a), "l"(b));
}
__device__ __forceinline__ float lo2(unsigned long long v) {
    return __uint_as_float((unsigned)(v & 0xffffffffULL));
}
__device__ __forceinline__ float hi2(unsigned long long v) {
    return __uint_as_float((unsigned)(v >> 32));
}

// ---------------------------------------------------------------------------
// K0: transpose main conv weights to [tap][c][oc] (one-time, tiny).
// ---------------------------------------------------------------------------
__global__ void k_wT(const float* __restrict__ wmain) {
    int t = blockIdx.x * blockDim.x + threadIdx.x;
    if (t >= 27 * CIN * COUT) return;
    int oc  = t & 31;
    int c   = (t >> 5) & 63;
    int tap = t >> 11;
    g_wT[t] = wmain[(oc * CIN + c) * 27 + tap];
}

// ---------------------------------------------------------------------------
// K1: parity-combined effective weights, [par][c][j][osec*28+oo] with
// zero padding so output channels are pair-contiguous for f32x2.
// ---------------------------------------------------------------------------
__global__ void k_weff(const float* __restrict__ w_off) {
    int t = blockIdx.x * blockDim.x + threadIdx.x;
    if (t >= 8 * CIN * 8 * OPAD) return;
    int o84  = t % OPAD;
    int j    = (t / OPAD) & 7;
    int c    = (t / (OPAD * 8)) & 63;
    int par  = t / (OPAD * 8 * CIN);
    int osec = o84 / 28, oo = o84 % 28;
    if (oo >= 27) { g_weff[t] = 0.f; return; }
    int o = osec * 27 + oo;
    int pd = (par >> 2) & 1, ph = (par >> 1) & 1, pw = par & 1;
    int jd = (j >> 2) & 1,  jh = (j >> 1) & 1,  jw = j & 1;
    int sd = jd * (1 + pd), nd = (pd != jd) ? 2 : 1;
    int sh = jh * (1 + ph), nh = (ph != jh) ? 2 : 1;
    int sw = jw * (1 + pw), nw = (pw != jw) ? 2 : 1;
    const float* wb = w_off + (o * CIN + c) * 27;
    float s = 0.f;
    for (int a = 0; a < nd; a++)
        for (int bq = 0; bq < nh; bq++)
            for (int cc = 0; cc < nw; cc++)
                s += wb[(sd + a) * 9 + (sh + bq) * 3 + (sw + cc)];
    g_weff[t] = s;
}

// ---------------------------------------------------------------------------
// K2: offset conv: 2-position register blocking + 3-way osec split +
// f32x2 accumulation. grid = 8 par x 16 tiles x 3 osec = 384, 128 thr.
// ---------------------------------------------------------------------------
__global__ void __launch_bounds__(128) k_offconv(const float* __restrict__ x,
                                                 const float* __restrict__ b_off) {
    __shared__ __align__(16) float sw[CCHUNK * 8 * 28];   // 14.3 KB
    int bid  = blockIdx.x;
    int par  = bid / 48;
    int rest = bid % 48;
    int tile = rest / 3;
    int osec = rest % 3;
    int ti   = threadIdx.x;
    int q0 = tile * 256 + ti;                 // and q0 + 128
    int pd = (par >> 2) & 1, ph = (par >> 1) & 1, pw = par & 1;

    int sp[2][8]; float msk[2][8];
    #pragma unroll
    for (int s = 0; s < 2; s++) {
        int q = q0 + s * 128;
        int qw = q & 15, qh = (q >> 4) & 15, qd = q >> 8;
        #pragma unroll
        for (int j = 0; j < 8; j++) {
            int cd = qd + pd - 1 + ((j >> 2) & 1);
            int ch = qh + ph - 1 + ((j >> 1) & 1);
            int cw = qw + pw - 1 + (j & 1);
            bool v = (unsigned)cd < 16u && (unsigned)ch < 16u && (unsigned)cw < 16u;
            sp[s][j]  = v ? ((cd * 16 + ch) * 16 + cw) : 0;
            msk[s][j] = v ? 1.f : 0.f;
        }
    }

    unsigned long long acc[2][14];
    #pragma unroll
    for (int s = 0; s < 2; s++)
        #pragma unroll
        for (int i = 0; i < 14; i++) acc[s][i] = 0ULL;

    #pragma unroll 1
    for (int c0 = 0; c0 < CIN; c0 += CCHUNK) {
        __syncthreads();
        for (int i = ti; i < CCHUNK * 8 * 28; i += 128) {
            int cc = i / (8 * 28);
            int ii = i % (8 * 28);
            int j  = ii / 28, oo = ii % 28;
            sw[i] = g_weff[(((size_t)(par * CIN + c0 + cc)) * 8 + j) * OPAD + osec * 28 + oo];
        }
        __syncthreads();
        #pragma unroll 1
        for (int cc = 0; cc < CCHUNK; cc++) {
            const float* xb = x + (c0 + cc) * NCELL;
            float xv[2][8];
            #pragma unroll
            for (int s = 0; s < 2; s++)
                #pragma unroll
                for (int j = 0; j < 8; j++)
                    xv[s][j] = msk[s][j] * __ldg(&xb[sp[s][j]]);
            #pragma unroll
            for (int j = 0; j < 8; j++) {
                unsigned long long x0 = pack2(xv[0][j]);
                unsigned long long x1 = pack2(xv[1][j]);
                const ulonglong2* wr = (const ulonglong2*)(sw + (cc * 8 + j) * 28);
                #pragma unroll
                for (int op = 0; op < 7; op++) {
                    ulonglong2 wp = wr[op];
                    fma2(acc[0][2*op],   x0, wp.x);
                    fma2(acc[0][2*op+1], x0, wp.y);
                    fma2(acc[1][2*op],   x1, wp.x);
                    fma2(acc[1][2*op+1], x1, wp.y);
                }
            }
        }
    }
    #pragma unroll
    for (int s = 0; s < 2; s++) {
        int q = q0 + s * 128;
        int qw = q & 15, qh = (q >> 4) & 15, qd = q >> 8;
        int df = 2*qd + pd, hf = 2*qh + ph, wf = 2*qw + pw;
        int p = (df * 32 + hf) * 32 + wf;
        #pragma unroll
        for (int i = 0; i < 14; i++) {
            int o0 = 2 * i, o1 = 2 * i + 1;
            g_off[(osec * 27 + o0) * NPOS + p] = lo2(acc[s][i]) + b_off[osec * 27 + o0];
            if (o1 < 27)
                g_off[(osec * 27 + o1) * NPOS + p] = hi2(acc[s][i]) + b_off[osec * 27 + o1];
        }
    }
}

// ---------------------------------------------------------------------------
// K3 helpers
// ---------------------------------------------------------------------------
__device__ __forceinline__ void sample16(const float* __restrict__ xbase,
                                         int tap, int kd, int kh, int kw,
                                         int p, float* samp) {
    int wf = p & 31, hf = (p >> 5) & 31, df = p >> 10;
    float pdc = (float)(df + kd - 1) + __ldg(&g_off[(tap * 3 + 0) * NPOS + p]);
    float phc = (float)(hf + kh - 1) + __ldg(&g_off[(tap * 3 + 1) * NPOS + p]);
    float pwc = (float)(wf + kw - 1) + __ldg(&g_off[(tap * 3 + 2) * NPOS + p]);
    float fd0 = floorf(pdc), fh0 = floorf(phc), fw0 = floorf(pwc);
    int id0 = (int)fd0, ih0 = (int)fh0, iw0 = (int)fw0;
    float fd = pdc - fd0, fh = phc - fh0, fw = pwc - fw0;

    int cD[2], cH[2], cW[2]; float wD[2], wH[2], wW[2];
    cD[0] = id0 >> 1; cD[1] = (id0 + 1) >> 1;
    cH[0] = ih0 >> 1; cH[1] = (ih0 + 1) >> 1;
    cW[0] = iw0 >> 1; cW[1] = (iw0 + 1) >> 1;
    bool ed = !(id0 & 1), eh = !(ih0 & 1), ew = !(iw0 & 1);
    wD[0] = ed ? 1.f : 1.f - fd;  wD[1] = ed ? 0.f : fd;
    wH[0] = eh ? 1.f : 1.f - fh;  wH[1] = eh ? 0.f : fh;
    wW[0] = ew ? 1.f : 1.f - fw;  wW[1] = ew ? 0.f : fw;
    if ((unsigned)cD[0] >= 16u) wD[0] = 0.f;
    if ((unsigned)cD[1] >= 16u) wD[1] = 0.f;
    if ((unsigned)cH[0] >= 16u) wH[0] = 0.f;
    if ((unsigned)cH[1] >= 16u) wH[1] = 0.f;
    if ((unsigned)cW[0] >= 16u) wW[0] = 0.f;
    if ((unsigned)cW[1] >= 16u) wW[1] = 0.f;

    #pragma unroll
    for (int i = 0; i < 16; i++) samp[i] = 0.f;

    #pragma unroll
    for (int jd = 0; jd < 2; jd++)
    #pragma unroll
    for (int jh = 0; jh < 2; jh++)
    #pragma unroll
    for (int jw = 0; jw < 2; jw++) {
        float wj = wD[jd] * wH[jh] * wW[jw];
        if (wj != 0.f) {
            const float* xb = xbase + ((cD[jd] * 16 + cH[jh]) * 16 + cW[jw]);
            #pragma unroll
            for (int cc = 0; cc < 16; cc++)
                samp[cc] += wj * __ldg(xb + cc * NCELL);
        }
    }
}

__device__ __forceinline__ void reduce_write(float* red, const float* acc,
                                             int cs, int posi, int p,
                                             const float* __restrict__ bmain,
                                             float* __restrict__ out) {
    __syncthreads();
    if (cs >= 2) {
        float* dst = red + ((cs - 2) * 64 + posi) * 33;
        #pragma unroll
        for (int oc = 0; oc < COUT; oc++) dst[oc] = acc[oc];
    }
    __syncthreads();
    float a2[COUT];
    if (cs < 2) {
        const float* src = red + (cs * 64 + posi) * 33;
        #pragma unroll
        for (int oc = 0; oc < COUT; oc++) a2[oc] = acc[oc] + src[oc];
    }
    __syncthreads();
    if (cs == 1) {
        float* dst = red + posi * 33;
        #pragma unroll
        for (int oc = 0; oc < COUT; oc++) dst[oc] = a2[oc];
    }
    __syncthreads();
    if (cs == 0) {
        const float* src = red + posi * 33;
        #pragma unroll
        for (int oc = 0; oc < COUT; oc++)
            out[oc * NPOS + p] = a2[oc] + src[oc] + bmain[oc];
    }
}

// ---------------------------------------------------------------------------
// K3: deformable conv, 2-position blocking + f32x2 contraction.
// Block = 128 positions x 4 channel quarters; grid = 256.
// ---------------------------------------------------------------------------
__global__ void __launch_bounds__(256, 2) k_deform(const float* __restrict__ x,
                                                   const float* __restrict__ bmain,
                                                   float* __restrict__ out) {
    __shared__ __align__(16) float ws[CIN * COUT];  // per-tap weights [c][oc], 8 KB
    __shared__ float red[2 * 64 * 33];              // reduction, padded
    int tid  = threadIdx.x;
    int posi = tid & 63;
    int cs   = tid >> 6;                      // channel quarter 0..3
    int p0 = blockIdx.x * 128 + posi;         // and p0 + 64

    unsigned long long acc0[16], acc1[16];
    #pragma unroll
    for (int i = 0; i < 16; i++) { acc0[i] = 0ULL; acc1[i] = 0ULL; }

    const float* xbase = x + cs * 16 * NCELL;

    #pragma unroll 1
    for (int tap = 0; tap < 27; tap++) {
        __syncthreads();
        {   // coalesced 8KB copy
            const float4* src = (const float4*)(g_wT + tap * CIN * COUT);
            float4* dst = (float4*)ws;
            for (int i = tid; i < CIN * COUT / 4; i += 256) dst[i] = src[i];
        }
        __syncthreads();

        int kd = tap / 9, kh = (tap / 3) % 3, kw = tap % 3;
        float samp0[16], samp1[16];
        sample16(xbase, tap, kd, kh, kw, p0,      samp0);
        sample16(xbase, tap, kd, kh, kw, p0 + 64, samp1);

        #pragma unroll
        for (int cc = 0; cc < 16; cc++) {
            unsigned long long v0 = pack2(samp0[cc]);
            unsigned long long v1 = pack2(samp1[cc]);
            const ulonglong2* wrow = (const ulonglong2*)(ws + (cs * 16 + cc) * 32);
            #pragma unroll
            for (int k = 0; k < 8; k++) {
                ulonglong2 wp = wrow[k];
                fma2(acc0[2*k],   v0, wp.x);
                fma2(acc0[2*k+1], v0, wp.y);
                fma2(acc1[2*k],   v1, wp.x);
                fma2(acc1[2*k+1], v1, wp.y);
            }
        }
    }

    float accf[COUT];
    #pragma unroll
    for (int i = 0; i < 16; i++) { accf[2*i] = lo2(acc0[i]); accf[2*i+1] = hi2(acc0[i]); }
    reduce_write(red, accf, cs, posi, p0, bmain, out);
    #pragma unroll
    for (int i = 0; i < 16; i++) { accf[2*i] = lo2(acc1[i]); accf[2*i+1] = hi2(acc1[i]); }
    reduce_write(red, accf, cs, posi, p0 + 64, bmain, out);
}

// ---------------------------------------------------------------------------
// K4a: per-channel mean/var -> scale/shift.  K4b: normalize + ReLU in place.
// ---------------------------------------------------------------------------
__global__ void __launch_bounds__(1024) k_bnstat(const float* __restrict__ out,
                                                 const float* __restrict__ gamma,
                                                 const float* __restrict__ beta) {
    __shared__ float ssum[1024], ssq[1024];
    int ch = blockIdx.x;
    const float* base = out + ch * NPOS;
    float s = 0.f, sq = 0.f;
    for (int i = threadIdx.x; i < NPOS; i += 1024) {
        float v = base[i];
        s += v; sq += v * v;
    }
    ssum[threadIdx.x] = s; ssq[threadIdx.x] = sq;
    __syncthreads();
    for (int st = 512; st > 0; st >>= 1) {
        if (threadIdx.x < st) {
            ssum[threadIdx.x] += ssum[threadIdx.x + st];
            ssq[threadIdx.x]  += ssq[threadIdx.x + st];
        }
        __syncthreads();
    }
    if (threadIdx.x == 0) {
        float mean = ssum[0] * (1.f / (float)NPOS);
        float var  = ssq[0] * (1.f / (float)NPOS) - mean * mean;
        float inv  = rsqrtf(var + 1e-5f);
        float a = gamma[ch] * inv;
        g_scale[ch] = a;
        g_shift[ch] = beta[ch] - mean * a;
    }
}

__global__ void k_bnapply(float* __restrict__ out) {
    int idx = blockIdx.x * 256 + threadIdx.x;
    int ch = idx >> 15;
    float v = out[idx] * g_scale[ch] + g_shift[ch];
    out[idx] = fmaxf(v, 0.f);
}

extern "C" void kernel_launch(void* const* d_in, const int* in_sizes, int n_in,
                              void* d_out, int out_size) {
    const float* x     = (const float*)d_in[0];   // (1,64,16,16,16)
    const float* w_off = (const float*)d_in[1];   // (81,64,3,3,3)
    const float* b_off = (const float*)d_in[2];   // (81,)
    const float* w     = (const float*)d_in[3];   // (32,64,3,3,3)
    const float* b     = (const float*)d_in[4];   // (32,)
    const float* gamma = (const float*)d_in[5];   // (32,)
    const float* beta  = (const float*)d_in[6];   // (32,)
    float* out = (float*)d_out;                   // (1,32,32,32,32)

    k_wT<<<(27 * CIN * COUT + 255) / 256, 256>>>(w);
    k_weff<<<(8 * CIN * 8 * OPAD + 255) / 256, 256>>>(w_off);
    k_offconv<<<384, 128>>>(x, b_off);
    k_deform<<<256, 256>>>(x, b, out);
    k_bnstat<<<COUT, 1024>>>(out, gamma, beta);
    k_bnapply<<<4096, 256>>>(out);
}